// round 15
// baseline (speedup 1.0000x reference)
#include <cuda_runtime.h>
#include <cuda_fp16.h>
#include <stdint.h>

#define NN 20000
#define NE 320000
#define DN 128
#define DE 128
#define DA 16
#define NH 256
#define NG 64
#define ST 12              // staging row stride in u32 words (8 used + 4 pad)
#define HST 132            // hidden smem row stride in words (128 + 4)
#define HFST 130           // hef fp32 smem row stride in words

// ---------------- scratch ----------------
__device__ float g_nproj[NN * 8];
__device__ float g_nsum[NN];
__device__ float g_nodefeat[NN * DE];
__device__ uint32_t g_xh[NN * 64];                        // x fp16x2 [n][kpair]
__device__ uint32_t g_nfh[NN * 64];                       // node_feat fp16x2
__device__ uint32_t g_ath[NE * 8];                        // attr fp16x2
__device__ uint32_t g_w1h[256 * 264];                     // W1 fp16, [n][kpair]
__device__ uint32_t g_w2h[128 * 128];                     // W2 fp16, [n][kpair]
__device__ uint32_t g_pnh[NN * 256];                      // node proj fp16x2: kp0..127=Pr, 128..255=Pc
__device__ float g_gsum[NG];
__device__ float g_graphfeat[NG * DE];

// ---------------- helpers ----------------
__device__ __forceinline__ float dot4(float4 a, float4 b) {
    return fmaf(a.x, b.x, fmaf(a.y, b.y, fmaf(a.z, b.z, a.w * b.w)));
}

__device__ __forceinline__ float wred(float v) {
    v += __shfl_xor_sync(0xffffffffu, v, 16);
    v += __shfl_xor_sync(0xffffffffu, v, 8);
    v += __shfl_xor_sync(0xffffffffu, v, 4);
    v += __shfl_xor_sync(0xffffffffu, v, 2);
    v += __shfl_xor_sync(0xffffffffu, v, 1);
    return v;
}

__device__ __forceinline__ uint32_t packhi16(float f0, float f1) {
    __half2 h = __floats2half2_rn(f0, f1);
    return *(uint32_t*)&h;
}

__device__ __forceinline__ void mma16f(float* c, const uint32_t* a, uint32_t b0, uint32_t b1) {
    asm volatile("mma.sync.aligned.m16n8k16.row.col.f32.f16.f16.f32 "
        "{%0,%1,%2,%3}, {%4,%5,%6,%7}, {%8,%9}, {%0,%1,%2,%3};"
        : "+f"(c[0]), "+f"(c[1]), "+f"(c[2]), "+f"(c[3])
        : "r"(a[0]), "r"(a[1]), "r"(a[2]), "r"(a[3]), "r"(b0), "r"(b1));
}

__device__ __forceinline__ void ldsm4(uint32_t* r, uint32_t addr) {
    asm volatile("ldmatrix.sync.aligned.m8n8.x4.shared.b16 {%0,%1,%2,%3}, [%4];"
        : "=r"(r[0]), "=r"(r[1]), "=r"(r[2]), "=r"(r[3]) : "r"(addr));
}

__device__ __forceinline__ void cpa16(uint32_t dst, const void* src) {
    asm volatile("cp.async.cg.shared.global [%0], [%1], 16;" :: "r"(dst), "l"(src) : "memory");
}
#define CP_COMMIT() asm volatile("cp.async.commit_group;" ::: "memory")
#define CP_WAIT0()  asm volatile("cp.async.wait_group 0;" ::: "memory")

// ---------------- prep: init scratch + pack x/attr + pack weights ----------------
__global__ void k_prep(const float* __restrict__ x, const float* __restrict__ attr,
                       const float* __restrict__ W1, const float* __restrict__ W2) {
    int i = blockIdx.x * 256 + threadIdx.x;
    if (i < NN * DE) g_nodefeat[i] = 0.f;
    if (i < NN) g_nsum[i] = 0.f;
    if (i < NG * DE) g_graphfeat[i] = 0.f;
    if (i < NG) g_gsum[i] = 0.f;
    if (i < NN * 64)
        g_xh[i] = packhi16(x[2 * i], x[2 * i + 1]);
    if (i < NE * 8)
        g_ath[i] = packhi16(attr[2 * i], attr[2 * i + 1]);
    if (i < 256 * 264) {
        int n = i / 264, kp = i % 264;
        g_w1h[i] = packhi16(W1[(2 * kp) * 256 + n], W1[(2 * kp + 1) * 256 + n]);
    }
    if (i < 128 * 128) {
        int n = i >> 7, kp = i & 127;
        g_w2h[i] = packhi16(W2[(2 * kp) * 128 + n], W2[(2 * kp + 1) * 128 + n]);
    }
}

// ---------------- per-node scalar projections ----------------
__global__ void k_nodeproj(const float* __restrict__ x, const float* __restrict__ Wagg,
                           const float* __restrict__ Wupd, const float* __restrict__ Wread) {
    int warp = threadIdx.x >> 5, lane = threadIdx.x & 31;
    int n = blockIdx.x * 8 + warp;
    if (n >= NN) return;
    float4 xv = ((const float4*)x)[n * 32 + lane];
    const float4* wa = (const float4*)Wagg;
    const float4* wu = (const float4*)Wupd;
    const float4* wr = (const float4*)Wread;
    float s0 = dot4(xv, wa[lane]);
    float s1 = dot4(xv, wa[32 + lane]);
    float s2 = dot4(xv, wu[lane]);
    float s3 = dot4(xv, wu[32 + lane]);
    float s4 = dot4(xv, wr[lane]);
    float s5 = dot4(xv, wr[32 + lane]);
    s0 = wred(s0); s1 = wred(s1); s2 = wred(s2);
    s3 = wred(s3); s4 = wred(s4); s5 = wred(s5);
    if (lane == 0) {
        g_nproj[n * 8 + 0] = s0; g_nproj[n * 8 + 1] = s1;
        g_nproj[n * 8 + 2] = s2; g_nproj[n * 8 + 3] = s3;
        g_nproj[n * 8 + 4] = s4; g_nproj[n * 8 + 5] = s5;
    }
}

// ---------------- agg logit + exp + scatter ----------------
__global__ void k_aggscatter(const float* __restrict__ hef, const float* __restrict__ attr,
                             const int* __restrict__ ei, const float* __restrict__ Wagg,
                             const float* __restrict__ bagg) {
    int warp = threadIdx.x >> 5, lane = threadIdx.x & 31;
    int e = blockIdx.x * 8 + warp;
    if (e >= NE) return;
    int r = ei[e], c = ei[NE + e];
    float4 h4 = ((const float4*)hef)[e * 32 + lane];
    float4 wh = *(const float4*)&Wagg[272 + lane * 4];
    float p = dot4(h4, wh);
    if (lane < 4) {
        float4 a4 = ((const float4*)attr)[e * 4 + lane];
        p += dot4(a4, *(const float4*)&Wagg[256 + lane * 4]);
    }
    p = wred(p);
    float w;
    if (lane == 0) {
        float logit = p + g_nproj[r * 8 + 0] + g_nproj[c * 8 + 1] + bagg[0];
        w = expf(logit);
        atomicAdd(&g_nsum[c], w);
    }
    w = __shfl_sync(0xffffffffu, w, 0);
    float* ptr = &g_nodefeat[c * 128 + lane * 4];
    asm volatile("red.global.add.v4.f32 [%0], {%1,%2,%3,%4};"
        :: "l"(ptr), "f"(w * h4.x), "f"(w * h4.y), "f"(w * h4.z), "f"(w * h4.w)
        : "memory");
}

// ---------------- normalize node_feat + pack fp16 ----------------
__global__ void k_nnorm() {
    int i = blockIdx.x * 256 + threadIdx.x;
    if (i >= NN * 64) return;
    int n = i >> 6;
    float inv = 1.f / (g_nsum[n] + 1e-16f);
    g_nfh[i] = packhi16(g_nodefeat[2 * i] * inv, g_nodefeat[2 * i + 1] * inv);
}

// ==================== NODE GEMM: P[n] = [x|nf][n] @ [W1[0:256] | W1[256:512]] ====================
#define NGM_WORDS 6144

__global__ void __launch_bounds__(256, 2)
k_nodegemm() {
    extern __shared__ uint32_t sm_[];
    int t = threadIdx.x;
    int mb0 = blockIdx.x * 128, hn0 = blockIdx.y * 128;

    int am = t >> 1, sw = (t & 1) * 4;
    int lane = t & 31, w = t >> 5;
    int wm = (w & 3) * 32, wn = (w >> 2) * 64;
    int grp = lane >> 2, quad = lane & 3;

    int n = mb0 + am; if (n >= NN) n = NN - 1;
    int np = hn0 + am;
    const uint32_t* bptr = (np < 256) ? (g_w1h + (size_t)np * 264)
                                      : (g_w1h + (size_t)(np - 256) * 264 + 128);

    uint32_t smb = (uint32_t)__cvta_generic_to_shared(sm_);
    int arow = wm + (lane & 15);
    uint32_t rA = smb + arow * (ST * 4) + ((lane & 16) ? 16 : 0);
    int brow = wn + (lane & 7) + ((lane & 16) ? 8 : 0);
    uint32_t rB = smb + 3072 * 4 + brow * (ST * 4) + ((lane & 8) ? 16 : 0);
    const uint32_t BUFB  = 1536 * 4;
    const uint32_t BHOFF = 3072 * 4;

    auto stage = [&](int kt, int buf) {
        int kp = kt * 8 + sw;
        const uint32_t* pa = (kp < 64) ? (g_xh + (size_t)n * 64 + kp)
                                       : (g_nfh + (size_t)n * 64 + kp - 64);
        uint32_t d = smb + (buf * 1536 + am * ST + sw) * 4;
        cpa16(d, pa);
        cpa16(d + BHOFF, bptr + kp);
    };

    stage(0, 0);
    CP_COMMIT();
    CP_WAIT0();
    __syncthreads();

    float acc[2][8][4];
#pragma unroll
    for (int i = 0; i < 2; i++)
#pragma unroll
        for (int j = 0; j < 8; j++)
#pragma unroll
            for (int k = 0; k < 4; k++) acc[i][j][k] = 0.f;

    const int KT = 16;
    for (int kt = 0; kt < KT; ++kt) {
        int cur = kt & 1;
        if (kt < KT - 1) {
            stage(kt + 1, cur ^ 1);
            CP_COMMIT();
        }
        uint32_t aH[2][4];
#pragma unroll
        for (int mf = 0; mf < 2; mf++)
            ldsm4(aH[mf], rA + cur * BUFB + mf * (16 * ST * 4));
#pragma unroll
        for (int j = 0; j < 4; j++) {
            uint32_t bH[4];
            ldsm4(bH, rB + cur * BUFB + j * (16 * ST * 4));
#pragma unroll
            for (int mf = 0; mf < 2; mf++) {
                mma16f(acc[mf][2 * j],     aH[mf], bH[0], bH[1]);
                mma16f(acc[mf][2 * j + 1], aH[mf], bH[2], bH[3]);
            }
        }
        if (kt < KT - 1) CP_WAIT0();
        __syncthreads();
    }

#pragma unroll
    for (int mf = 0; mf < 2; mf++) {
        int m = mb0 + wm + mf * 16 + grp;
#pragma unroll
        for (int nf = 0; nf < 8; nf++) {
            int c0 = hn0 + wn + nf * 8 + quad * 2;
            int kp = c0 >> 1;
            if (m < NN)
                g_pnh[(size_t)m * 256 + kp] = packhi16(acc[mf][nf][0], acc[mf][nf][1]);
            if (m + 8 < NN)
                g_pnh[(size_t)(m + 8) * 256 + kp] = packhi16(acc[mf][nf][2], acc[mf][nf][3]);
        }
    }
}

// ==================== EDGE FUSED: hidden -> cand -> gate -> ef(out) -> readout scatter ====================
// smem words: SA 1536 @0 | SB 2x1536 @1536 | Hs/hefF/sacc region @4608 (16896) |
//             srol @21504 scol @21632 sred @21760 sg @22016  -> 22144 words (86.5 KB)
#define SA_W    0
#define SB_W    1536
#define HS_W    4608
#define EF_WORDS 22144

__global__ void __launch_bounds__(256, 2)
k_edge(const float* __restrict__ hef, const int* __restrict__ ei,
       const int* __restrict__ batch,
       const float* __restrict__ b1, const float* __restrict__ b2,
       const float* __restrict__ Wupd, const float* __restrict__ bupd,
       const float* __restrict__ Wread, const float* __restrict__ bread,
       float* __restrict__ out) {
    extern __shared__ uint32_t sm_[];
    int*   srol = (int*)(sm_ + 21504);
    int*   scol = (int*)(sm_ + 21632);
    float* sred = (float*)(sm_ + 21760);
    float* sg   = (float*)(sm_ + 22016);

    int t = threadIdx.x;
    int me0 = blockIdx.x * 128;
    if (t < 128) srol[t] = ei[me0 + t];
    else scol[t - 128] = ei[NE + me0 + t - 128];

    int am = t >> 1, sw = (t & 1) * 4;
    int lane = t & 31, w = t >> 5;
    int wm = (w & 3) * 32, wn = (w >> 2) * 64;
    int grp = lane >> 2, quad = lane & 3;

    uint32_t smb = (uint32_t)__cvta_generic_to_shared(sm_);
    int arow = wm + (lane & 15);
    int brow = wn + (lane & 7) + ((lane & 16) ? 8 : 0);
    uint32_t rSA = smb + SA_W * 4 + arow * (ST * 4) + ((lane & 16) ? 16 : 0);
    uint32_t rSB = smb + SB_W * 4 + brow * (ST * 4) + ((lane & 8) ? 16 : 0);
    uint32_t rHs = smb + HS_W * 4 + arow * (HST * 4) + ((lane & 16) ? 16 : 0);
    const uint32_t BUFB = 1536 * 4;

    // ---- phase A staging: attr A-tile + both W1-attr B half-tiles ----
    {
        uint32_t d = smb + (SA_W + am * ST + sw) * 4;
        cpa16(d, g_ath + (size_t)(me0 + am) * 8 + sw);
        cpa16(smb + (SB_W + am * ST + sw) * 4,
              g_w1h + (size_t)am * 264 + 256 + sw);
        cpa16(smb + (SB_W + 1536 + am * ST + sw) * 4,
              g_w1h + (size_t)(128 + am) * 264 + 256 + sw);
    }
    CP_COMMIT();
    CP_WAIT0();
    __syncthreads();

    float acc[2][8][4];

    // ---- phase A: hidden = relu(attr@W1attr + Pr[rol] + Pc[col] + b1) -> Hs ----
#pragma unroll
    for (int half = 0; half < 2; half++) {
#pragma unroll
        for (int i = 0; i < 2; i++)
#pragma unroll
            for (int j = 0; j < 8; j++)
#pragma unroll
                for (int k = 0; k < 4; k++) acc[i][j][k] = 0.f;

        uint32_t aH[2][4];
#pragma unroll
        for (int mf = 0; mf < 2; mf++)
            ldsm4(aH[mf], rSA + mf * (16 * ST * 4));
#pragma unroll
        for (int j = 0; j < 4; j++) {
            uint32_t bH[4];
            ldsm4(bH, rSB + half * BUFB + j * (16 * ST * 4));
#pragma unroll
            for (int mf = 0; mf < 2; mf++) {
                mma16f(acc[mf][2 * j],     aH[mf], bH[0], bH[1]);
                mma16f(acc[mf][2 * j + 1], aH[mf], bH[2], bH[3]);
            }
        }

#pragma unroll
        for (int mf = 0; mf < 2; mf++) {
            int ml0 = wm + mf * 16 + grp;
            int r0 = srol[ml0], c0n = scol[ml0];
            int r1 = srol[ml0 + 8], c1n = scol[ml0 + 8];
#pragma unroll
            for (int nf = 0; nf < 8; nf++) {
                int c = half * 128 + wn + nf * 8 + quad * 2;
                int kp = c >> 1;
                float2 bb = *(const float2*)&b1[c];
                float2 pr0 = __half22float2(*(const __half2*)&g_pnh[(size_t)r0 * 256 + kp]);
                float2 pc0 = __half22float2(*(const __half2*)&g_pnh[(size_t)c0n * 256 + 128 + kp]);
                float v0 = fmaxf(acc[mf][nf][0] + pr0.x + pc0.x + bb.x, 0.f);
                float v1 = fmaxf(acc[mf][nf][1] + pr0.y + pc0.y + bb.y, 0.f);
                sm_[HS_W + ml0 * HST + kp] = packhi16(v0, v1);
                float2 pr1 = __half22float2(*(const __half2*)&g_pnh[(size_t)r1 * 256 + kp]);
                float2 pc1 = __half22float2(*(const __half2*)&g_pnh[(size_t)c1n * 256 + 128 + kp]);
                float v2 = fmaxf(acc[mf][nf][2] + pr1.x + pc1.x + bb.x, 0.f);
                float v3 = fmaxf(acc[mf][nf][3] + pr1.y + pc1.y + bb.y, 0.f);
                sm_[HS_W + (ml0 + 8) * HST + kp] = packhi16(v2, v3);
            }
        }
    }
    __syncthreads();

    // ---- phase B: cand = hidden @ W2 ----
    auto stageB = [&](int kt, int buf) {
        int kp = kt * 8 + sw;
        cpa16(smb + (SB_W + buf * 1536 + am * ST + sw) * 4,
              g_w2h + (size_t)am * 128 + kp);
    };

    stageB(0, 0);
    CP_COMMIT();
    CP_WAIT0();
    __syncthreads();

#pragma unroll
    for (int i = 0; i < 2; i++)
#pragma unroll
        for (int j = 0; j < 8; j++)
#pragma unroll
            for (int k = 0; k < 4; k++) acc[i][j][k] = 0.f;

    const int KT = NH / 16;
    for (int kt = 0; kt < KT; ++kt) {
        int cur = kt & 1;
        if (kt < KT - 1) {
            stageB(kt + 1, cur ^ 1);
            CP_COMMIT();
        }
        uint32_t aH[2][4];
#pragma unroll
        for (int mf = 0; mf < 2; mf++)
            ldsm4(aH[mf], rHs + kt * 32 + mf * (16 * HST * 4));
#pragma unroll
        for (int j = 0; j < 4; j++) {
            uint32_t bH[4];
            ldsm4(bH, rSB + cur * BUFB + j * (16 * ST * 4));
#pragma unroll
            for (int mf = 0; mf < 2; mf++) {
                mma16f(acc[mf][2 * j],     aH[mf], bH[0], bH[1]);
                mma16f(acc[mf][2 * j + 1], aH[mf], bH[2], bH[3]);
            }
        }
        if (kt < KT - 1) CP_WAIT0();
        __syncthreads();
    }

    // acc += b2 -> cand
#pragma unroll
    for (int mf = 0; mf < 2; mf++)
#pragma unroll
        for (int nf = 0; nf < 8; nf++) {
            int c0 = wn + nf * 8 + quad * 2;
            float bb0 = b2[c0], bb1 = b2[c0 + 1];
            acc[mf][nf][0] += bb0; acc[mf][nf][1] += bb1;
            acc[mf][nf][2] += bb0; acc[mf][nf][3] += bb1;
        }

    float* hefF = (float*)(sm_ + HS_W);   // Hs dead after mainloop; stash hef fp32 here
    float prd = 0.f;                       // per-edge readout attr dot (t<128 lanes)

    // ---- epilogue pass 1: gate logit dot + stash hef tile in smem ----
    float s0 = 0.f, s1 = 0.f, s2 = 0.f, s3 = 0.f;
#pragma unroll
    for (int mf = 0; mf < 2; mf++) {
        int r0 = wm + mf * 16 + grp;
#pragma unroll
        for (int nf = 0; nf < 8; nf++) {
            int c = wn + nf * 8 + quad * 2;
            float2 wc = *(const float2*)&Wupd[400 + c];
            float2 whv = *(const float2*)&Wupd[272 + c];
            float2 h0 = *(const float2*)&hef[(size_t)(me0 + r0) * 128 + c];
            float2 h1 = *(const float2*)&hef[(size_t)(me0 + r0 + 8) * 128 + c];
            *(float2*)&hefF[r0 * HFST + c] = h0;
            *(float2*)&hefF[(r0 + 8) * HFST + c] = h1;
            float p0 = acc[mf][nf][0] * wc.x + acc[mf][nf][1] * wc.y + h0.x * whv.x + h0.y * whv.y;
            float p1 = acc[mf][nf][2] * wc.x + acc[mf][nf][3] * wc.y + h1.x * whv.x + h1.y * whv.y;
            if (mf == 0) { s0 += p0; s1 += p1; } else { s2 += p0; s3 += p1; }
        }
    }
    s0 += __shfl_xor_sync(0xffffffffu, s0, 1); s0 += __shfl_xor_sync(0xffffffffu, s0, 2);
    s1 += __shfl_xor_sync(0xffffffffu, s1, 1); s1 += __shfl_xor_sync(0xffffffffu, s1, 2);
    s2 += __shfl_xor_sync(0xffffffffu, s2, 1); s2 += __shfl_xor_sync(0xffffffffu, s2, 2);
    s3 += __shfl_xor_sync(0xffffffffu, s3, 1); s3 += __shfl_xor_sync(0xffffffffu, s3, 2);
    if (quad == 0) {
        int nh = w >> 2;
        sred[(wm + grp) * 2 + nh] = s0;
        sred[(wm + 8 + grp) * 2 + nh] = s1;
        sred[(wm + 16 + grp) * 2 + nh] = s2;
        sred[(wm + 24 + grp) * 2 + nh] = s3;
    }
    __syncthreads();
    if (t < 128) {
        // attr-dot projections for gate/readout from staged fp16 attr
        float pu = 0.f;
#pragma unroll
        for (int i = 0; i < 8; i++) {
            float2 a2 = __half22float2(*(const __half2*)&sm_[SA_W + t * ST + i]);
            pu  = fmaf(a2.x, Wupd[256 + 2 * i],  fmaf(a2.y, Wupd[256 + 2 * i + 1],  pu));
            prd = fmaf(a2.x, Wread[384 + 2 * i], fmaf(a2.y, Wread[384 + 2 * i + 1], prd));
        }
        int r = srol[t], c = scol[t];
        float tot = sred[t * 2] + sred[t * 2 + 1];
        float gv = tot + pu + g_nproj[r * 8 + 2] + g_nproj[c * 8 + 3] + bupd[0];
        sg[t] = 1.f / (1.f + expf(-gv));
    }
    __syncthreads();

    // ---- epilogue pass 2: ef = g*cand + (1-g)*hef (into acc), write out, readout dot ----
    s0 = s1 = s2 = s3 = 0.f;
#pragma unroll
    for (int mf = 0; mf < 2; mf++) {
        int r0 = wm + mf * 16 + grp;
        float g0 = sg[r0], g1 = sg[r0 + 8];
#pragma unroll
        for (int nf = 0; nf < 8; nf++) {
            int c = wn + nf * 8 + quad * 2;
            float2 h0 = *(const float2*)&hefF[r0 * HFST + c];
            float2 h1 = *(const float2*)&hefF[(r0 + 8) * HFST + c];
            float2 e0, e1;
            e0.x = fmaf(g0, acc[mf][nf][0] - h0.x, h0.x);
            e0.y = fmaf(g0, acc[mf][nf][1] - h0.y, h0.y);
            e1.x = fmaf(g1, acc[mf][nf][2] - h1.x, h1.x);
            e1.y = fmaf(g1, acc[mf][nf][3] - h1.y, h1.y);
            acc[mf][nf][0] = e0.x; acc[mf][nf][1] = e0.y;   // acc now holds ef
            acc[mf][nf][2] = e1.x; acc[mf][nf][3] = e1.y;
            *(float2*)&out[(size_t)(me0 + r0) * 128 + c] = e0;
            *(float2*)&out[(size_t)(me0 + r0 + 8) * 128 + c] = e1;
            float2 wr = *(const float2*)&Wread[256 + c];
            float p0 = e0.x * wr.x + e0.y * wr.y;
            float p1 = e1.x * wr.x + e1.y * wr.y;
            if (mf == 0) { s0 += p0; s1 += p1; } else { s2 += p0; s3 += p1; }
        }
    }
    s0 += __shfl_xor_sync(0xffffffffu, s0, 1); s0 += __shfl_xor_sync(0xffffffffu, s0, 2);
    s1 += __shfl_xor_sync(0xffffffffu, s1, 1); s1 += __shfl_xor_sync(0xffffffffu, s1, 2);
    s2 += __shfl_xor_sync(0xffffffffu, s2, 1); s2 += __shfl_xor_sync(0xffffffffu, s2, 2);
    s3 += __shfl_xor_sync(0xffffffffu, s3, 1); s3 += __shfl_xor_sync(0xffffffffu, s3, 2);
    if (quad == 0) {
        int nh = w >> 2;
        sred[(wm + grp) * 2 + nh] = s0;
        sred[(wm + 8 + grp) * 2 + nh] = s1;
        sred[(wm + 16 + grp) * 2 + nh] = s2;
        sred[(wm + 24 + grp) * 2 + nh] = s3;
    }
    __syncthreads();
    if (t < 128) {
        int r = srol[t], c = scol[t];
        float tot = sred[t * 2] + sred[t * 2 + 1];
        float rl = tot + prd + g_nproj[r * 8 + 4] + g_nproj[c * 8 + 5] + bread[0];
        sg[t] = expf(rl);                 // sg now holds rw
    }
    __syncthreads();

    // ---- readout scatter: sacc[gi][c] += rw * ef (smem), then merge to global ----
    float* sacc = (float*)(sm_ + HS_W);          // 8192 f (overwrites hefF - done with it)
    float* ssum = (float*)(sm_ + HS_W + 8192);   // 64 f
    int*   sgi  = (int*)(sm_ + HS_W + 8256);     // 128 i
    for (int i = t; i < NG * DE; i += 256) sacc[i] = 0.f;
    if (t < NG) ssum[t] = 0.f;
    if (t < 128) sgi[t] = batch[srol[t]];
    __syncthreads();

#pragma unroll
    for (int mf = 0; mf < 2; mf++) {
        int r0 = wm + mf * 16 + grp;
        float rw0 = sg[r0], rw1 = sg[r0 + 8];
        int gi0 = sgi[r0] * 128, gi1 = sgi[r0 + 8] * 128;
#pragma unroll
        for (int nf = 0; nf < 8; nf++) {
            int c = wn + nf * 8 + quad * 2;
            atomicAdd(&sacc[gi0 + c],     rw0 * acc[mf][nf][0]);
            atomicAdd(&sacc[gi0 + c + 1], rw0 * acc[mf][nf][1]);
            atomicAdd(&sacc[gi1 + c],     rw1 * acc[mf][nf][2]);
            atomicAdd(&sacc[gi1 + c + 1], rw1 * acc[mf][nf][3]);
        }
    }
    if (t < 128) atomicAdd(&ssum[sgi[t]], sg[t]);
    __syncthreads();

    for (int i = t; i < NG * DE; i += 256)
        if (sacc[i] != 0.f) atomicAdd(&g_graphfeat[i], sacc[i]);
    if (t < NG && ssum[t] != 0.f) atomicAdd(&g_gsum[t], ssum[t]);
}

// ---------------- confidence ----------------
__global__ void k_conf(const float* __restrict__ Wscore, const float* __restrict__ bscore,
                       float* __restrict__ out) {
    int g = blockIdx.x, t = threadIdx.x;
    float v = g_graphfeat[g * 128 + t] / (g_gsum[g] + 1e-16f) * Wscore[t];
    v = wred(v);
    __shared__ float sm[4];
    if ((t & 31) == 0) sm[t >> 5] = v;
    __syncthreads();
    if (t == 0) {
        float s = sm[0] + sm[1] + sm[2] + sm[3] + bscore[0];
        out[(size_t)NE * DE + g] = 1.f / (1.f + expf(-s));
    }
}

// ---------------- launch ----------------
extern "C" void kernel_launch(void* const* d_in, const int* in_sizes, int n_in,
                              void* d_out, int out_size) {
    const float* x      = (const float*)d_in[0];
    const float* hef    = (const float*)d_in[1];
    const float* attr   = (const float*)d_in[2];
    const int*   ei     = (const int*)d_in[3];
    const int*   batch  = (const int*)d_in[4];
    const float* Wagg   = (const float*)d_in[6];
    const float* bagg   = (const float*)d_in[7];
    const float* W1     = (const float*)d_in[8];
    const float* b1     = (const float*)d_in[9];
    const float* W2     = (const float*)d_in[10];
    const float* b2     = (const float*)d_in[11];
    const float* Wupd   = (const float*)d_in[12];
    const float* bupd   = (const float*)d_in[13];
    const float* Wread  = (const float*)d_in[14];
    const float* bread  = (const float*)d_in[15];
    const float* Wscore = (const float*)d_in[16];
    const float* bscore = (const float*)d_in[17];
    float* out = (float*)d_out;

    static bool attr_set = false;
    if (!attr_set) {
        cudaFuncSetAttribute(k_nodegemm, cudaFuncAttributeMaxDynamicSharedMemorySize, NGM_WORDS * 4);
        cudaFuncSetAttribute(k_edge, cudaFuncAttributeMaxDynamicSharedMemorySize, EF_WORDS * 4);
        attr_set = true;
    }

    k_prep<<<(NE * 8 + 255) / 256, 256>>>(x, attr, W1, W2);
    k_nodeproj<<<(NN + 7) / 8, 256>>>(x, Wagg, Wupd, Wread);
    k_aggscatter<<<NE / 8, 256>>>(hef, attr, ei, Wagg, bagg);
    k_nnorm<<<(NN * 64 + 255) / 256, 256>>>();
    k_nodegemm<<<dim3((NN + 127) / 128, 4), 256, NGM_WORDS * 4>>>();
    k_edge<<<NE / 128, 256, EF_WORDS * 4>>>(hef, ei, batch, b1, b2, Wupd, bupd,
                                            Wread, bread, out);
    k_conf<<<NG, 128>>>(Wscore, bscore, out);
}

// round 16
// speedup vs baseline: 1.0185x; 1.0185x over previous
#include <cuda_runtime.h>
#include <cuda_fp16.h>
#include <stdint.h>

#define NN 20000
#define NE 320000
#define DN 128
#define DE 128
#define DA 16
#define NH 256
#define NG 64
#define ST 12              // staging row stride in u32 words (8 used + 4 pad)
#define HST 132            // hidden smem row stride in words (128 + 4)
#define HFST 130           // hef fp32 smem row stride in words

// ---------------- scratch ----------------
__device__ float g_nproj[NN * 8];
__device__ float g_nsum[NN];
__device__ float g_nodefeat[NN * DE];
__device__ uint32_t g_xh[NN * 64];                        // x fp16x2 [n][kpair]
__device__ uint32_t g_nfh[NN * 64];                       // node_feat fp16x2
__device__ uint32_t g_ath[NE * 8];                        // attr fp16x2
__device__ uint32_t g_w1h[256 * 264];                     // W1 fp16, [n][kpair]
__device__ uint32_t g_w2h[128 * 128];                     // W2 fp16, [n][kpair]
__device__ uint32_t g_pnh[NN * 256];                      // node proj fp16x2: kp0..127=Pr, 128..255=Pc
__device__ float g_rw[NE];
__device__ float g_gsum[NG];
__device__ float g_graphfeat[NG * DE];

// ---------------- helpers ----------------
__device__ __forceinline__ float dot4(float4 a, float4 b) {
    return fmaf(a.x, b.x, fmaf(a.y, b.y, fmaf(a.z, b.z, a.w * b.w)));
}

__device__ __forceinline__ float wred(float v) {
    v += __shfl_xor_sync(0xffffffffu, v, 16);
    v += __shfl_xor_sync(0xffffffffu, v, 8);
    v += __shfl_xor_sync(0xffffffffu, v, 4);
    v += __shfl_xor_sync(0xffffffffu, v, 2);
    v += __shfl_xor_sync(0xffffffffu, v, 1);
    return v;
}

__device__ __forceinline__ uint32_t packhi16(float f0, float f1) {
    __half2 h = __floats2half2_rn(f0, f1);
    return *(uint32_t*)&h;
}

__device__ __forceinline__ void mma16f(float* c, const uint32_t* a, uint32_t b0, uint32_t b1) {
    asm volatile("mma.sync.aligned.m16n8k16.row.col.f32.f16.f16.f32 "
        "{%0,%1,%2,%3}, {%4,%5,%6,%7}, {%8,%9}, {%0,%1,%2,%3};"
        : "+f"(c[0]), "+f"(c[1]), "+f"(c[2]), "+f"(c[3])
        : "r"(a[0]), "r"(a[1]), "r"(a[2]), "r"(a[3]), "r"(b0), "r"(b1));
}

__device__ __forceinline__ void ldsm4(uint32_t* r, uint32_t addr) {
    asm volatile("ldmatrix.sync.aligned.m8n8.x4.shared.b16 {%0,%1,%2,%3}, [%4];"
        : "=r"(r[0]), "=r"(r[1]), "=r"(r[2]), "=r"(r[3]) : "r"(addr));
}

__device__ __forceinline__ void cpa16(uint32_t dst, const void* src) {
    asm volatile("cp.async.cg.shared.global [%0], [%1], 16;" :: "r"(dst), "l"(src) : "memory");
}
#define CP_COMMIT() asm volatile("cp.async.commit_group;" ::: "memory")
#define CP_WAIT0()  asm volatile("cp.async.wait_group 0;" ::: "memory")

// ---------------- prep: init scratch + pack x/attr + pack weights ----------------
__global__ void k_prep(const float* __restrict__ x, const float* __restrict__ attr,
                       const float* __restrict__ W1, const float* __restrict__ W2) {
    int i = blockIdx.x * 256 + threadIdx.x;
    if (i < NN * DE) g_nodefeat[i] = 0.f;
    if (i < NN) g_nsum[i] = 0.f;
    if (i < NG * DE) g_graphfeat[i] = 0.f;
    if (i < NG) g_gsum[i] = 0.f;
    if (i < NN * 64)
        g_xh[i] = packhi16(x[2 * i], x[2 * i + 1]);
    if (i < NE * 8)
        g_ath[i] = packhi16(attr[2 * i], attr[2 * i + 1]);
    if (i < 256 * 264) {
        int n = i / 264, kp = i % 264;
        g_w1h[i] = packhi16(W1[(2 * kp) * 256 + n], W1[(2 * kp + 1) * 256 + n]);
    }
    if (i < 128 * 128) {
        int n = i >> 7, kp = i & 127;
        g_w2h[i] = packhi16(W2[(2 * kp) * 128 + n], W2[(2 * kp + 1) * 128 + n]);
    }
}

// ---------------- per-node scalar projections ----------------
__global__ void k_nodeproj(const float* __restrict__ x, const float* __restrict__ Wagg,
                           const float* __restrict__ Wupd, const float* __restrict__ Wread) {
    int warp = threadIdx.x >> 5, lane = threadIdx.x & 31;
    int n = blockIdx.x * 8 + warp;
    if (n >= NN) return;
    float4 xv = ((const float4*)x)[n * 32 + lane];
    const float4* wa = (const float4*)Wagg;
    const float4* wu = (const float4*)Wupd;
    const float4* wr = (const float4*)Wread;
    float s0 = dot4(xv, wa[lane]);
    float s1 = dot4(xv, wa[32 + lane]);
    float s2 = dot4(xv, wu[lane]);
    float s3 = dot4(xv, wu[32 + lane]);
    float s4 = dot4(xv, wr[lane]);
    float s5 = dot4(xv, wr[32 + lane]);
    s0 = wred(s0); s1 = wred(s1); s2 = wred(s2);
    s3 = wred(s3); s4 = wred(s4); s5 = wred(s5);
    if (lane == 0) {
        g_nproj[n * 8 + 0] = s0; g_nproj[n * 8 + 1] = s1;
        g_nproj[n * 8 + 2] = s2; g_nproj[n * 8 + 3] = s3;
        g_nproj[n * 8 + 4] = s4; g_nproj[n * 8 + 5] = s5;
    }
}

// ---------------- agg logit + exp + scatter ----------------
__global__ void k_aggscatter(const float* __restrict__ hef, const float* __restrict__ attr,
                             const int* __restrict__ ei, const float* __restrict__ Wagg,
                             const float* __restrict__ bagg) {
    int warp = threadIdx.x >> 5, lane = threadIdx.x & 31;
    int e = blockIdx.x * 8 + warp;
    if (e >= NE) return;
    int r = ei[e], c = ei[NE + e];
    float4 h4 = ((const float4*)hef)[e * 32 + lane];
    float4 wh = *(const float4*)&Wagg[272 + lane * 4];
    float p = dot4(h4, wh);
    if (lane < 4) {
        float4 a4 = ((const float4*)attr)[e * 4 + lane];
        p += dot4(a4, *(const float4*)&Wagg[256 + lane * 4]);
    }
    p = wred(p);
    float w;
    if (lane == 0) {
        float logit = p + g_nproj[r * 8 + 0] + g_nproj[c * 8 + 1] + bagg[0];
        w = expf(logit);
        atomicAdd(&g_nsum[c], w);
    }
    w = __shfl_sync(0xffffffffu, w, 0);
    float* ptr = &g_nodefeat[c * 128 + lane * 4];
    asm volatile("red.global.add.v4.f32 [%0], {%1,%2,%3,%4};"
        :: "l"(ptr), "f"(w * h4.x), "f"(w * h4.y), "f"(w * h4.z), "f"(w * h4.w)
        : "memory");
}

// ---------------- normalize node_feat + pack fp16 ----------------
__global__ void k_nnorm() {
    int i = blockIdx.x * 256 + threadIdx.x;
    if (i >= NN * 64) return;
    int n = i >> 6;
    float inv = 1.f / (g_nsum[n] + 1e-16f);
    g_nfh[i] = packhi16(g_nodefeat[2 * i] * inv, g_nodefeat[2 * i + 1] * inv);
}

// ==================== NODE GEMM: P[n] = [x|nf][n] @ [W1[0:256] | W1[256:512]] ====================
#define NGM_WORDS 6144

__global__ void __launch_bounds__(256, 2)
k_nodegemm() {
    extern __shared__ uint32_t sm_[];
    int t = threadIdx.x;
    int mb0 = blockIdx.x * 128, hn0 = blockIdx.y * 128;

    int am = t >> 1, sw = (t & 1) * 4;
    int lane = t & 31, w = t >> 5;
    int wm = (w & 3) * 32, wn = (w >> 2) * 64;
    int grp = lane >> 2, quad = lane & 3;

    int n = mb0 + am; if (n >= NN) n = NN - 1;
    int np = hn0 + am;
    const uint32_t* bptr = (np < 256) ? (g_w1h + (size_t)np * 264)
                                      : (g_w1h + (size_t)(np - 256) * 264 + 128);

    uint32_t smb = (uint32_t)__cvta_generic_to_shared(sm_);
    int arow = wm + (lane & 15);
    uint32_t rA = smb + arow * (ST * 4) + ((lane & 16) ? 16 : 0);
    int brow = wn + (lane & 7) + ((lane & 16) ? 8 : 0);
    uint32_t rB = smb + 3072 * 4 + brow * (ST * 4) + ((lane & 8) ? 16 : 0);
    const uint32_t BUFB  = 1536 * 4;
    const uint32_t BHOFF = 3072 * 4;

    auto stage = [&](int kt, int buf) {
        int kp = kt * 8 + sw;
        const uint32_t* pa = (kp < 64) ? (g_xh + (size_t)n * 64 + kp)
                                       : (g_nfh + (size_t)n * 64 + kp - 64);
        uint32_t d = smb + (buf * 1536 + am * ST + sw) * 4;
        cpa16(d, pa);
        cpa16(d + BHOFF, bptr + kp);
    };

    stage(0, 0);
    CP_COMMIT();
    CP_WAIT0();
    __syncthreads();

    float acc[2][8][4];
#pragma unroll
    for (int i = 0; i < 2; i++)
#pragma unroll
        for (int j = 0; j < 8; j++)
#pragma unroll
            for (int k = 0; k < 4; k++) acc[i][j][k] = 0.f;

    const int KT = 16;
    for (int kt = 0; kt < KT; ++kt) {
        int cur = kt & 1;
        if (kt < KT - 1) {
            stage(kt + 1, cur ^ 1);
            CP_COMMIT();
        }
        uint32_t aH[2][4];
#pragma unroll
        for (int mf = 0; mf < 2; mf++)
            ldsm4(aH[mf], rA + cur * BUFB + mf * (16 * ST * 4));
#pragma unroll
        for (int j = 0; j < 4; j++) {
            uint32_t bH[4];
            ldsm4(bH, rB + cur * BUFB + j * (16 * ST * 4));
#pragma unroll
            for (int mf = 0; mf < 2; mf++) {
                mma16f(acc[mf][2 * j],     aH[mf], bH[0], bH[1]);
                mma16f(acc[mf][2 * j + 1], aH[mf], bH[2], bH[3]);
            }
        }
        if (kt < KT - 1) CP_WAIT0();
        __syncthreads();
    }

#pragma unroll
    for (int mf = 0; mf < 2; mf++) {
        int m = mb0 + wm + mf * 16 + grp;
#pragma unroll
        for (int nf = 0; nf < 8; nf++) {
            int c0 = hn0 + wn + nf * 8 + quad * 2;
            int kp = c0 >> 1;
            if (m < NN)
                g_pnh[(size_t)m * 256 + kp] = packhi16(acc[mf][nf][0], acc[mf][nf][1]);
            if (m + 8 < NN)
                g_pnh[(size_t)(m + 8) * 256 + kp] = packhi16(acc[mf][nf][2], acc[mf][nf][3]);
        }
    }
}

// ==================== EDGE FUSED: hidden -> cand -> gate -> ef(out) -> readout exp ====================
// smem words: SA 1536 @0 | SB 2x1536 @1536 | Hs/hefF region @4608 (16896) |
//             srol @21504 scol @21632 sred @21760 sg @22016  -> 22144 words (86.5 KB)
#define SA_W    0
#define SB_W    1536
#define HS_W    4608
#define EF_WORDS 22144

__global__ void __launch_bounds__(256, 2)
k_edge(const float* __restrict__ hef, const int* __restrict__ ei,
       const float* __restrict__ b1, const float* __restrict__ b2,
       const float* __restrict__ Wupd, const float* __restrict__ bupd,
       const float* __restrict__ Wread, const float* __restrict__ bread,
       float* __restrict__ out) {
    extern __shared__ uint32_t sm_[];
    int*   srol = (int*)(sm_ + 21504);
    int*   scol = (int*)(sm_ + 21632);
    float* sred = (float*)(sm_ + 21760);
    float* sg   = (float*)(sm_ + 22016);

    int t = threadIdx.x;
    int me0 = blockIdx.x * 128;
    if (t < 128) srol[t] = ei[me0 + t];
    else scol[t - 128] = ei[NE + me0 + t - 128];

    int am = t >> 1, sw = (t & 1) * 4;
    int lane = t & 31, w = t >> 5;
    int wm = (w & 3) * 32, wn = (w >> 2) * 64;
    int grp = lane >> 2, quad = lane & 3;

    uint32_t smb = (uint32_t)__cvta_generic_to_shared(sm_);
    int arow = wm + (lane & 15);
    int brow = wn + (lane & 7) + ((lane & 16) ? 8 : 0);
    uint32_t rSA = smb + SA_W * 4 + arow * (ST * 4) + ((lane & 16) ? 16 : 0);
    uint32_t rSB = smb + SB_W * 4 + brow * (ST * 4) + ((lane & 8) ? 16 : 0);
    uint32_t rHs = smb + HS_W * 4 + arow * (HST * 4) + ((lane & 16) ? 16 : 0);
    const uint32_t BUFB = 1536 * 4;

    // ---- phase A staging: attr A-tile + both W1-attr B half-tiles ----
    {
        uint32_t d = smb + (SA_W + am * ST + sw) * 4;
        cpa16(d, g_ath + (size_t)(me0 + am) * 8 + sw);
        cpa16(smb + (SB_W + am * ST + sw) * 4,
              g_w1h + (size_t)am * 264 + 256 + sw);
        cpa16(smb + (SB_W + 1536 + am * ST + sw) * 4,
              g_w1h + (size_t)(128 + am) * 264 + 256 + sw);
    }
    CP_COMMIT();
    CP_WAIT0();
    __syncthreads();

    float acc[2][8][4];

    // ---- phase A: hidden = relu(attr@W1attr + Pr[rol] + Pc[col] + b1) -> Hs ----
#pragma unroll
    for (int half = 0; half < 2; half++) {
#pragma unroll
        for (int i = 0; i < 2; i++)
#pragma unroll
            for (int j = 0; j < 8; j++)
#pragma unroll
                for (int k = 0; k < 4; k++) acc[i][j][k] = 0.f;

        uint32_t aH[2][4];
#pragma unroll
        for (int mf = 0; mf < 2; mf++)
            ldsm4(aH[mf], rSA + mf * (16 * ST * 4));
#pragma unroll
        for (int j = 0; j < 4; j++) {
            uint32_t bH[4];
            ldsm4(bH, rSB + half * BUFB + j * (16 * ST * 4));
#pragma unroll
            for (int mf = 0; mf < 2; mf++) {
                mma16f(acc[mf][2 * j],     aH[mf], bH[0], bH[1]);
                mma16f(acc[mf][2 * j + 1], aH[mf], bH[2], bH[3]);
            }
        }

#pragma unroll
        for (int mf = 0; mf < 2; mf++) {
            int ml0 = wm + mf * 16 + grp;
            int r0 = srol[ml0], c0n = scol[ml0];
            int r1 = srol[ml0 + 8], c1n = scol[ml0 + 8];
#pragma unroll
            for (int nf = 0; nf < 8; nf++) {
                int c = half * 128 + wn + nf * 8 + quad * 2;
                int kp = c >> 1;
                float2 bb = *(const float2*)&b1[c];
                float2 pr0 = __half22float2(*(const __half2*)&g_pnh[(size_t)r0 * 256 + kp]);
                float2 pc0 = __half22float2(*(const __half2*)&g_pnh[(size_t)c0n * 256 + 128 + kp]);
                float v0 = fmaxf(acc[mf][nf][0] + pr0.x + pc0.x + bb.x, 0.f);
                float v1 = fmaxf(acc[mf][nf][1] + pr0.y + pc0.y + bb.y, 0.f);
                sm_[HS_W + ml0 * HST + kp] = packhi16(v0, v1);
                float2 pr1 = __half22float2(*(const __half2*)&g_pnh[(size_t)r1 * 256 + kp]);
                float2 pc1 = __half22float2(*(const __half2*)&g_pnh[(size_t)c1n * 256 + 128 + kp]);
                float v2 = fmaxf(acc[mf][nf][2] + pr1.x + pc1.x + bb.x, 0.f);
                float v3 = fmaxf(acc[mf][nf][3] + pr1.y + pc1.y + bb.y, 0.f);
                sm_[HS_W + (ml0 + 8) * HST + kp] = packhi16(v2, v3);
            }
        }
    }
    __syncthreads();

    // ---- phase B: cand = hidden @ W2 ----
    auto stageB = [&](int kt, int buf) {
        int kp = kt * 8 + sw;
        cpa16(smb + (SB_W + buf * 1536 + am * ST + sw) * 4,
              g_w2h + (size_t)am * 128 + kp);
    };

    stageB(0, 0);
    CP_COMMIT();
    CP_WAIT0();
    __syncthreads();

#pragma unroll
    for (int i = 0; i < 2; i++)
#pragma unroll
        for (int j = 0; j < 8; j++)
#pragma unroll
            for (int k = 0; k < 4; k++) acc[i][j][k] = 0.f;

    const int KT = NH / 16;
    for (int kt = 0; kt < KT; ++kt) {
        int cur = kt & 1;
        if (kt < KT - 1) {
            stageB(kt + 1, cur ^ 1);
            CP_COMMIT();
        }
        uint32_t aH[2][4];
#pragma unroll
        for (int mf = 0; mf < 2; mf++)
            ldsm4(aH[mf], rHs + kt * 32 + mf * (16 * HST * 4));
#pragma unroll
        for (int j = 0; j < 4; j++) {
            uint32_t bH[4];
            ldsm4(bH, rSB + cur * BUFB + j * (16 * ST * 4));
#pragma unroll
            for (int mf = 0; mf < 2; mf++) {
                mma16f(acc[mf][2 * j],     aH[mf], bH[0], bH[1]);
                mma16f(acc[mf][2 * j + 1], aH[mf], bH[2], bH[3]);
            }
        }
        if (kt < KT - 1) CP_WAIT0();
        __syncthreads();
    }

    // acc += b2 -> cand
#pragma unroll
    for (int mf = 0; mf < 2; mf++)
#pragma unroll
        for (int nf = 0; nf < 8; nf++) {
            int c0 = wn + nf * 8 + quad * 2;
            float bb0 = b2[c0], bb1 = b2[c0 + 1];
            acc[mf][nf][0] += bb0; acc[mf][nf][1] += bb1;
            acc[mf][nf][2] += bb0; acc[mf][nf][3] += bb1;
        }

    float* hefF = (float*)(sm_ + HS_W);   // Hs dead after mainloop; stash hef fp32 here
    float prd = 0.f;                       // per-edge readout attr dot (t<128 lanes)

    // ---- epilogue pass 1: gate logit dot + stash hef tile in smem ----
    float s0 = 0.f, s1 = 0.f, s2 = 0.f, s3 = 0.f;
#pragma unroll
    for (int mf = 0; mf < 2; mf++) {
        int r0 = wm + mf * 16 + grp;
#pragma unroll
        for (int nf = 0; nf < 8; nf++) {
            int c = wn + nf * 8 + quad * 2;
            float2 wc = *(const float2*)&Wupd[400 + c];
            float2 whv = *(const float2*)&Wupd[272 + c];
            float2 h0 = *(const float2*)&hef[(size_t)(me0 + r0) * 128 + c];
            float2 h1 = *(const float2*)&hef[(size_t)(me0 + r0 + 8) * 128 + c];
            *(float2*)&hefF[r0 * HFST + c] = h0;
            *(float2*)&hefF[(r0 + 8) * HFST + c] = h1;
            float p0 = acc[mf][nf][0] * wc.x + acc[mf][nf][1] * wc.y + h0.x * whv.x + h0.y * whv.y;
            float p1 = acc[mf][nf][2] * wc.x + acc[mf][nf][3] * wc.y + h1.x * whv.x + h1.y * whv.y;
            if (mf == 0) { s0 += p0; s1 += p1; } else { s2 += p0; s3 += p1; }
        }
    }
    s0 += __shfl_xor_sync(0xffffffffu, s0, 1); s0 += __shfl_xor_sync(0xffffffffu, s0, 2);
    s1 += __shfl_xor_sync(0xffffffffu, s1, 1); s1 += __shfl_xor_sync(0xffffffffu, s1, 2);
    s2 += __shfl_xor_sync(0xffffffffu, s2, 1); s2 += __shfl_xor_sync(0xffffffffu, s2, 2);
    s3 += __shfl_xor_sync(0xffffffffu, s3, 1); s3 += __shfl_xor_sync(0xffffffffu, s3, 2);
    if (quad == 0) {
        int nh = w >> 2;
        sred[(wm + grp) * 2 + nh] = s0;
        sred[(wm + 8 + grp) * 2 + nh] = s1;
        sred[(wm + 16 + grp) * 2 + nh] = s2;
        sred[(wm + 24 + grp) * 2 + nh] = s3;
    }
    __syncthreads();
    if (t < 128) {
        float pu = 0.f;
#pragma unroll
        for (int i = 0; i < 8; i++) {
            float2 a2 = __half22float2(*(const __half2*)&sm_[SA_W + t * ST + i]);
            pu  = fmaf(a2.x, Wupd[256 + 2 * i],  fmaf(a2.y, Wupd[256 + 2 * i + 1],  pu));
            prd = fmaf(a2.x, Wread[384 + 2 * i], fmaf(a2.y, Wread[384 + 2 * i + 1], prd));
        }
        int r = srol[t], c = scol[t];
        float tot = sred[t * 2] + sred[t * 2 + 1];
        float gv = tot + pu + g_nproj[r * 8 + 2] + g_nproj[c * 8 + 3] + bupd[0];
        sg[t] = 1.f / (1.f + expf(-gv));
    }
    __syncthreads();

    // ---- epilogue pass 2: ef = g*cand + (1-g)*hef, write out, readout dot ----
    s0 = s1 = s2 = s3 = 0.f;
#pragma unroll
    for (int mf = 0; mf < 2; mf++) {
        int r0 = wm + mf * 16 + grp;
        float g0 = sg[r0], g1 = sg[r0 + 8];
#pragma unroll
        for (int nf = 0; nf < 8; nf++) {
            int c = wn + nf * 8 + quad * 2;
            float2 h0 = *(const float2*)&hefF[r0 * HFST + c];
            float2 h1 = *(const float2*)&hefF[(r0 + 8) * HFST + c];
            float2 e0, e1;
            e0.x = fmaf(g0, acc[mf][nf][0] - h0.x, h0.x);
            e0.y = fmaf(g0, acc[mf][nf][1] - h0.y, h0.y);
            e1.x = fmaf(g1, acc[mf][nf][2] - h1.x, h1.x);
            e1.y = fmaf(g1, acc[mf][nf][3] - h1.y, h1.y);
            *(float2*)&out[(size_t)(me0 + r0) * 128 + c] = e0;
            *(float2*)&out[(size_t)(me0 + r0 + 8) * 128 + c] = e1;
            float2 wr = *(const float2*)&Wread[256 + c];
            float p0 = e0.x * wr.x + e0.y * wr.y;
            float p1 = e1.x * wr.x + e1.y * wr.y;
            if (mf == 0) { s0 += p0; s1 += p1; } else { s2 += p0; s3 += p1; }
        }
    }
    s0 += __shfl_xor_sync(0xffffffffu, s0, 1); s0 += __shfl_xor_sync(0xffffffffu, s0, 2);
    s1 += __shfl_xor_sync(0xffffffffu, s1, 1); s1 += __shfl_xor_sync(0xffffffffu, s1, 2);
    s2 += __shfl_xor_sync(0xffffffffu, s2, 1); s2 += __shfl_xor_sync(0xffffffffu, s2, 2);
    s3 += __shfl_xor_sync(0xffffffffu, s3, 1); s3 += __shfl_xor_sync(0xffffffffu, s3, 2);
    if (quad == 0) {
        int nh = w >> 2;
        sred[(wm + grp) * 2 + nh] = s0;
        sred[(wm + 8 + grp) * 2 + nh] = s1;
        sred[(wm + 16 + grp) * 2 + nh] = s2;
        sred[(wm + 24 + grp) * 2 + nh] = s3;
    }
    __syncthreads();
    if (t < 128) {
        int e = me0 + t, r = srol[t], c = scol[t];
        float tot = sred[t * 2] + sred[t * 2 + 1];
        float rl = tot + prd + g_nproj[r * 8 + 4] + g_nproj[c * 8 + 5] + bread[0];
        g_rw[e] = expf(rl);
    }
}

// ---------------- readout: unnormalized scatter + segment sum ----------------
__global__ void k_rscatter(const int* __restrict__ ei, const int* __restrict__ batch,
                           const float* __restrict__ out) {
    __shared__ float sacc[NG * DE];
    __shared__ float ssum[NG];
    int t = threadIdx.x;
    for (int i = t; i < NG * DE; i += 256) sacc[i] = 0.f;
    if (t < NG) ssum[t] = 0.f;
    __syncthreads();
    int warp = t >> 5, lane = t & 31;
    for (int e = blockIdx.x * 8 + warp; e < NE; e += gridDim.x * 8) {
        int gi = batch[ei[e]];
        float rw = g_rw[e];
        float4 ef = ((const float4*)out)[e * 32 + lane];
        float* p = &sacc[gi * 128 + lane * 4];
        atomicAdd(p + 0, rw * ef.x);
        atomicAdd(p + 1, rw * ef.y);
        atomicAdd(p + 2, rw * ef.z);
        atomicAdd(p + 3, rw * ef.w);
        if (lane == 0) atomicAdd(&ssum[gi], rw);
    }
    __syncthreads();
    for (int i = t; i < NG * DE; i += 256)
        if (sacc[i] != 0.f) atomicAdd(&g_graphfeat[i], sacc[i]);
    if (t < NG && ssum[t] != 0.f) atomicAdd(&g_gsum[t], ssum[t]);
}

// ---------------- confidence ----------------
__global__ void k_conf(const float* __restrict__ Wscore, const float* __restrict__ bscore,
                       float* __restrict__ out) {
    int g = blockIdx.x, t = threadIdx.x;
    float v = g_graphfeat[g * 128 + t] / (g_gsum[g] + 1e-16f) * Wscore[t];
    v = wred(v);
    __shared__ float sm[4];
    if ((t & 31) == 0) sm[t >> 5] = v;
    __syncthreads();
    if (t == 0) {
        float s = sm[0] + sm[1] + sm[2] + sm[3] + bscore[0];
        out[(size_t)NE * DE + g] = 1.f / (1.f + expf(-s));
    }
}

// ---------------- launch ----------------
extern "C" void kernel_launch(void* const* d_in, const int* in_sizes, int n_in,
                              void* d_out, int out_size) {
    const float* x      = (const float*)d_in[0];
    const float* hef    = (const float*)d_in[1];
    const float* attr   = (const float*)d_in[2];
    const int*   ei     = (const int*)d_in[3];
    const int*   batch  = (const int*)d_in[4];
    const float* Wagg   = (const float*)d_in[6];
    const float* bagg   = (const float*)d_in[7];
    const float* W1     = (const float*)d_in[8];
    const float* b1     = (const float*)d_in[9];
    const float* W2     = (const float*)d_in[10];
    const float* b2     = (const float*)d_in[11];
    const float* Wupd   = (const float*)d_in[12];
    const float* bupd   = (const float*)d_in[13];
    const float* Wread  = (const float*)d_in[14];
    const float* bread  = (const float*)d_in[15];
    const float* Wscore = (const float*)d_in[16];
    const float* bscore = (const float*)d_in[17];
    float* out = (float*)d_out;

    static bool attr_set = false;
    if (!attr_set) {
        cudaFuncSetAttribute(k_nodegemm, cudaFuncAttributeMaxDynamicSharedMemorySize, NGM_WORDS * 4);
        cudaFuncSetAttribute(k_edge, cudaFuncAttributeMaxDynamicSharedMemorySize, EF_WORDS * 4);
        attr_set = true;
    }

    k_prep<<<(NE * 8 + 255) / 256, 256>>>(x, attr, W1, W2);
    k_nodeproj<<<(NN + 7) / 8, 256>>>(x, Wagg, Wupd, Wread);
    k_aggscatter<<<NE / 8, 256>>>(hef, attr, ei, Wagg, bagg);
    k_nnorm<<<(NN * 64 + 255) / 256, 256>>>();
    k_nodegemm<<<dim3((NN + 127) / 128, 4), 256, NGM_WORDS * 4>>>();
    k_edge<<<NE / 128, 256, EF_WORDS * 4>>>(hef, ei, b1, b2, Wupd, bupd,
                                            Wread, bread, out);
    k_rscatter<<<296, 256>>>(ei, batch, out);
    k_conf<<<NG, 128>>>(Wscore, bscore, out);
}

// round 17
// speedup vs baseline: 1.0324x; 1.0136x over previous
#include <cuda_runtime.h>
#include <cuda_fp16.h>
#include <stdint.h>

#define NN 20000
#define NE 320000
#define DN 128
#define DE 128
#define DA 16
#define NH 256
#define NG 64
#define ST 12              // staging row stride in u32 words (8 used + 4 pad)
#define HST 132            // hidden smem row stride in words (128 + 4)

// ---------------- scratch ----------------
__device__ float g_nproj[NN * 8];
__device__ float g_eproj[NE * 4];      // [0]=pu+hu (gate non-cand), [1]=pr, [2]=hr
__device__ float g_nsum[NN];
__device__ float g_nodefeat[NN * DE];
__device__ uint32_t g_xh[NN * 64];
__device__ uint32_t g_nfh[NN * 64];
__device__ uint32_t g_ath[NE * 8];
__device__ uint32_t g_w1h[256 * 264];
__device__ uint32_t g_w2h[128 * 128];
__device__ uint32_t g_pnh[NN * 256];   // node proj fp16x2: kp0..127=Pr, 128..255=Pc
__device__ float g_rw[NE];
__device__ float g_gsum[NG];
__device__ float g_graphfeat[NG * DE];

// ---------------- helpers ----------------
__device__ __forceinline__ float dot4(float4 a, float4 b) {
    return fmaf(a.x, b.x, fmaf(a.y, b.y, fmaf(a.z, b.z, a.w * b.w)));
}

__device__ __forceinline__ float wred(float v) {
    v += __shfl_xor_sync(0xffffffffu, v, 16);
    v += __shfl_xor_sync(0xffffffffu, v, 8);
    v += __shfl_xor_sync(0xffffffffu, v, 4);
    v += __shfl_xor_sync(0xffffffffu, v, 2);
    v += __shfl_xor_sync(0xffffffffu, v, 1);
    return v;
}

__device__ __forceinline__ uint32_t packhi16(float f0, float f1) {
    __half2 h = __floats2half2_rn(f0, f1);
    return *(uint32_t*)&h;
}

__device__ __forceinline__ void mma16f(float* c, const uint32_t* a, uint32_t b0, uint32_t b1) {
    asm volatile("mma.sync.aligned.m16n8k16.row.col.f32.f16.f16.f32 "
        "{%0,%1,%2,%3}, {%4,%5,%6,%7}, {%8,%9}, {%0,%1,%2,%3};"
        : "+f"(c[0]), "+f"(c[1]), "+f"(c[2]), "+f"(c[3])
        : "r"(a[0]), "r"(a[1]), "r"(a[2]), "r"(a[3]), "r"(b0), "r"(b1));
}

__device__ __forceinline__ void ldsm4(uint32_t* r, uint32_t addr) {
    asm volatile("ldmatrix.sync.aligned.m8n8.x4.shared.b16 {%0,%1,%2,%3}, [%4];"
        : "=r"(r[0]), "=r"(r[1]), "=r"(r[2]), "=r"(r[3]) : "r"(addr));
}

__device__ __forceinline__ void cpa16(uint32_t dst, const void* src) {
    asm volatile("cp.async.cg.shared.global [%0], [%1], 16;" :: "r"(dst), "l"(src) : "memory");
}
#define CP_COMMIT() asm volatile("cp.async.commit_group;" ::: "memory")
#define CP_WAIT0()  asm volatile("cp.async.wait_group 0;" ::: "memory")

// ---------------- prep: init + packs + node scalar projections (merged) ----------------
__global__ void k_prep(const float* __restrict__ x, const float* __restrict__ attr,
                       const float* __restrict__ W1, const float* __restrict__ W2,
                       const float* __restrict__ Wagg, const float* __restrict__ Wupd,
                       const float* __restrict__ Wread) {
    int i = blockIdx.x * 256 + threadIdx.x;
    if (i < NN * DE) g_nodefeat[i] = 0.f;
    if (i < NN) g_nsum[i] = 0.f;
    if (i < NG * DE) g_graphfeat[i] = 0.f;
    if (i < NG) g_gsum[i] = 0.f;
    if (i < NN * 64)
        g_xh[i] = packhi16(x[2 * i], x[2 * i + 1]);
    if (i < NE * 8)
        g_ath[i] = packhi16(attr[2 * i], attr[2 * i + 1]);
    if (i < 256 * 264) {
        int n = i / 264, kp = i % 264;
        g_w1h[i] = packhi16(W1[(2 * kp) * 256 + n], W1[(2 * kp + 1) * 256 + n]);
    }
    if (i < 128 * 128) {
        int n = i >> 7, kp = i & 127;
        g_w2h[i] = packhi16(W2[(2 * kp) * 128 + n], W2[(2 * kp + 1) * 128 + n]);
    }

    // node scalar projections (warp per node; blocks 0..2499 active)
    int warp = threadIdx.x >> 5, lane = threadIdx.x & 31;
    int n = blockIdx.x * 8 + warp;
    if (n < NN) {
        float4 xv = ((const float4*)x)[n * 32 + lane];
        const float4* wa = (const float4*)Wagg;
        const float4* wu = (const float4*)Wupd;
        const float4* wr = (const float4*)Wread;
        float s0 = dot4(xv, wa[lane]);
        float s1 = dot4(xv, wa[32 + lane]);
        float s2 = dot4(xv, wu[lane]);
        float s3 = dot4(xv, wu[32 + lane]);
        float s4 = dot4(xv, wr[lane]);
        float s5 = dot4(xv, wr[32 + lane]);
        s0 = wred(s0); s1 = wred(s1); s2 = wred(s2);
        s3 = wred(s3); s4 = wred(s4); s5 = wred(s5);
        if (lane == 0) {
            g_nproj[n * 8 + 0] = s0; g_nproj[n * 8 + 1] = s1;
            g_nproj[n * 8 + 2] = s2; g_nproj[n * 8 + 3] = s3;
            g_nproj[n * 8 + 4] = s4; g_nproj[n * 8 + 5] = s5;
        }
    }
}

// ---------------- agg logit + exp + scatter + hef/attr projections ----------------
__global__ void k_aggscatter(const float* __restrict__ hef, const float* __restrict__ attr,
                             const int* __restrict__ ei, const float* __restrict__ Wagg,
                             const float* __restrict__ bagg, const float* __restrict__ Wupd,
                             const float* __restrict__ Wread) {
    int warp = threadIdx.x >> 5, lane = threadIdx.x & 31;
    int e = blockIdx.x * 8 + warp;
    if (e >= NE) return;
    int r = ei[e], c = ei[NE + e];
    float4 h4 = ((const float4*)hef)[e * 32 + lane];
    float p  = dot4(h4, *(const float4*)&Wagg[272 + lane * 4]);
    float hu = dot4(h4, *(const float4*)&Wupd[272 + lane * 4]);
    float hr = dot4(h4, *(const float4*)&Wread[256 + lane * 4]);
    float pu = 0.f, pr = 0.f;
    if (lane < 4) {
        float4 a4 = ((const float4*)attr)[e * 4 + lane];
        p  += dot4(a4, *(const float4*)&Wagg[256 + lane * 4]);
        pu  = dot4(a4, *(const float4*)&Wupd[256 + lane * 4]);
        pr  = dot4(a4, *(const float4*)&Wread[384 + lane * 4]);
    }
    p = wred(p); hu = wred(hu); hr = wred(hr); pu = wred(pu); pr = wred(pr);
    float w;
    if (lane == 0) {
        float logit = p + g_nproj[r * 8 + 0] + g_nproj[c * 8 + 1] + bagg[0];
        w = expf(logit);
        g_eproj[e * 4 + 0] = pu + hu;
        g_eproj[e * 4 + 1] = pr;
        g_eproj[e * 4 + 2] = hr;
        atomicAdd(&g_nsum[c], w);
    }
    w = __shfl_sync(0xffffffffu, w, 0);
    float* ptr = &g_nodefeat[c * 128 + lane * 4];
    asm volatile("red.global.add.v4.f32 [%0], {%1,%2,%3,%4};"
        :: "l"(ptr), "f"(w * h4.x), "f"(w * h4.y), "f"(w * h4.z), "f"(w * h4.w)
        : "memory");
}

// ---------------- normalize node_feat + pack fp16 ----------------
__global__ void k_nnorm() {
    int i = blockIdx.x * 256 + threadIdx.x;
    if (i >= NN * 64) return;
    int n = i >> 6;
    float inv = 1.f / (g_nsum[n] + 1e-16f);
    g_nfh[i] = packhi16(g_nodefeat[2 * i] * inv, g_nodefeat[2 * i + 1] * inv);
}

// ==================== NODE GEMM: P[n] = [x|nf][n] @ [W1[0:256] | W1[256:512]] ====================
#define NGM_WORDS 6144

__global__ void __launch_bounds__(256, 2)
k_nodegemm() {
    extern __shared__ uint32_t sm_[];
    int t = threadIdx.x;
    int mb0 = blockIdx.x * 128, hn0 = blockIdx.y * 128;

    int am = t >> 1, sw = (t & 1) * 4;
    int lane = t & 31, w = t >> 5;
    int wm = (w & 3) * 32, wn = (w >> 2) * 64;
    int grp = lane >> 2, quad = lane & 3;

    int n = mb0 + am; if (n >= NN) n = NN - 1;
    int np = hn0 + am;
    const uint32_t* bptr = (np < 256) ? (g_w1h + (size_t)np * 264)
                                      : (g_w1h + (size_t)(np - 256) * 264 + 128);

    uint32_t smb = (uint32_t)__cvta_generic_to_shared(sm_);
    int arow = wm + (lane & 15);
    uint32_t rA = smb + arow * (ST * 4) + ((lane & 16) ? 16 : 0);
    int brow = wn + (lane & 7) + ((lane & 16) ? 8 : 0);
    uint32_t rB = smb + 3072 * 4 + brow * (ST * 4) + ((lane & 8) ? 16 : 0);
    const uint32_t BUFB  = 1536 * 4;
    const uint32_t BHOFF = 3072 * 4;

    auto stage = [&](int kt, int buf) {
        int kp = kt * 8 + sw;
        const uint32_t* pa = (kp < 64) ? (g_xh + (size_t)n * 64 + kp)
                                       : (g_nfh + (size_t)n * 64 + kp - 64);
        uint32_t d = smb + (buf * 1536 + am * ST + sw) * 4;
        cpa16(d, pa);
        cpa16(d + BHOFF, bptr + kp);
    };

    stage(0, 0);
    CP_COMMIT();
    CP_WAIT0();
    __syncthreads();

    float acc[2][8][4];
#pragma unroll
    for (int i = 0; i < 2; i++)
#pragma unroll
        for (int j = 0; j < 8; j++)
#pragma unroll
            for (int k = 0; k < 4; k++) acc[i][j][k] = 0.f;

    const int KT = 16;
    for (int kt = 0; kt < KT; ++kt) {
        int cur = kt & 1;
        if (kt < KT - 1) {
            stage(kt + 1, cur ^ 1);
            CP_COMMIT();
        }
        uint32_t aH[2][4];
#pragma unroll
        for (int mf = 0; mf < 2; mf++)
            ldsm4(aH[mf], rA + cur * BUFB + mf * (16 * ST * 4));
#pragma unroll
        for (int j = 0; j < 4; j++) {
            uint32_t bH[4];
            ldsm4(bH, rB + cur * BUFB + j * (16 * ST * 4));
#pragma unroll
            for (int mf = 0; mf < 2; mf++) {
                mma16f(acc[mf][2 * j],     aH[mf], bH[0], bH[1]);
                mma16f(acc[mf][2 * j + 1], aH[mf], bH[2], bH[3]);
            }
        }
        if (kt < KT - 1) CP_WAIT0();
        __syncthreads();
    }

#pragma unroll
    for (int mf = 0; mf < 2; mf++) {
        int m = mb0 + wm + mf * 16 + grp;
#pragma unroll
        for (int nf = 0; nf < 8; nf++) {
            int c0 = hn0 + wn + nf * 8 + quad * 2;
            int kp = c0 >> 1;
            if (m < NN)
                g_pnh[(size_t)m * 256 + kp] = packhi16(acc[mf][nf][0], acc[mf][nf][1]);
            if (m + 8 < NN)
                g_pnh[(size_t)(m + 8) * 256 + kp] = packhi16(acc[mf][nf][2], acc[mf][nf][3]);
        }
    }
}

// ==================== EDGE FUSED: hidden -> cand -> gate/readout (hef-free) -> ef(out) ====================
// smem words: SA 1536 @0 | SB 2x1536 @1536 | Hs @4608 (16896) |
//             srol @21504 scol @21632 sred @21760 (512) sg @22272 (128) -> 22400 words
#define SA_W    0
#define SB_W    1536
#define HS_W    4608
#define EF_WORDS 22400

__global__ void __launch_bounds__(256, 2)
k_edge(const float* __restrict__ hef, const int* __restrict__ ei,
       const float* __restrict__ b1, const float* __restrict__ b2,
       const float* __restrict__ Wupd, const float* __restrict__ bupd,
       const float* __restrict__ Wread, const float* __restrict__ bread,
       float* __restrict__ out) {
    extern __shared__ uint32_t sm_[];
    int*   srol = (int*)(sm_ + 21504);
    int*   scol = (int*)(sm_ + 21632);
    float* sred = (float*)(sm_ + 21760);
    float* sg   = (float*)(sm_ + 22272);

    int t = threadIdx.x;
    int me0 = blockIdx.x * 128;
    if (t < 128) srol[t] = ei[me0 + t];
    else scol[t - 128] = ei[NE + me0 + t - 128];

    int am = t >> 1, sw = (t & 1) * 4;
    int lane = t & 31, w = t >> 5;
    int wm = (w & 3) * 32, wn = (w >> 2) * 64;
    int grp = lane >> 2, quad = lane & 3;

    uint32_t smb = (uint32_t)__cvta_generic_to_shared(sm_);
    int arow = wm + (lane & 15);
    int brow = wn + (lane & 7) + ((lane & 16) ? 8 : 0);
    uint32_t rSA = smb + SA_W * 4 + arow * (ST * 4) + ((lane & 16) ? 16 : 0);
    uint32_t rSB = smb + SB_W * 4 + brow * (ST * 4) + ((lane & 8) ? 16 : 0);
    uint32_t rHs = smb + HS_W * 4 + arow * (HST * 4) + ((lane & 16) ? 16 : 0);
    const uint32_t BUFB = 1536 * 4;

    // ---- phase A staging: attr A-tile + both W1-attr B half-tiles ----
    {
        uint32_t d = smb + (SA_W + am * ST + sw) * 4;
        cpa16(d, g_ath + (size_t)(me0 + am) * 8 + sw);
        cpa16(smb + (SB_W + am * ST + sw) * 4,
              g_w1h + (size_t)am * 264 + 256 + sw);
        cpa16(smb + (SB_W + 1536 + am * ST + sw) * 4,
              g_w1h + (size_t)(128 + am) * 264 + 256 + sw);
    }
    CP_COMMIT();
    CP_WAIT0();
    __syncthreads();

    float acc[2][8][4];

    // ---- phase A: hidden = relu(attr@W1attr + Pr[rol] + Pc[col] + b1) -> Hs ----
#pragma unroll
    for (int half = 0; half < 2; half++) {
#pragma unroll
        for (int i = 0; i < 2; i++)
#pragma unroll
            for (int j = 0; j < 8; j++)
#pragma unroll
                for (int k = 0; k < 4; k++) acc[i][j][k] = 0.f;

        uint32_t aH[2][4];
#pragma unroll
        for (int mf = 0; mf < 2; mf++)
            ldsm4(aH[mf], rSA + mf * (16 * ST * 4));
#pragma unroll
        for (int j = 0; j < 4; j++) {
            uint32_t bH[4];
            ldsm4(bH, rSB + half * BUFB + j * (16 * ST * 4));
#pragma unroll
            for (int mf = 0; mf < 2; mf++) {
                mma16f(acc[mf][2 * j],     aH[mf], bH[0], bH[1]);
                mma16f(acc[mf][2 * j + 1], aH[mf], bH[2], bH[3]);
            }
        }

#pragma unroll
        for (int mf = 0; mf < 2; mf++) {
            int ml0 = wm + mf * 16 + grp;
            int r0 = srol[ml0], c0n = scol[ml0];
            int r1 = srol[ml0 + 8], c1n = scol[ml0 + 8];
#pragma unroll
            for (int nf = 0; nf < 8; nf++) {
                int c = half * 128 + wn + nf * 8 + quad * 2;
                int kp = c >> 1;
                float2 bb = *(const float2*)&b1[c];
                float2 pr0 = __half22float2(*(const __half2*)&g_pnh[(size_t)r0 * 256 + kp]);
                float2 pc0 = __half22float2(*(const __half2*)&g_pnh[(size_t)c0n * 256 + 128 + kp]);
                float v0 = fmaxf(acc[mf][nf][0] + pr0.x + pc0.x + bb.x, 0.f);
                float v1 = fmaxf(acc[mf][nf][1] + pr0.y + pc0.y + bb.y, 0.f);
                sm_[HS_W + ml0 * HST + kp] = packhi16(v0, v1);
                float2 pr1 = __half22float2(*(const __half2*)&g_pnh[(size_t)r1 * 256 + kp]);
                float2 pc1 = __half22float2(*(const __half2*)&g_pnh[(size_t)c1n * 256 + 128 + kp]);
                float v2 = fmaxf(acc[mf][nf][2] + pr1.x + pc1.x + bb.x, 0.f);
                float v3 = fmaxf(acc[mf][nf][3] + pr1.y + pc1.y + bb.y, 0.f);
                sm_[HS_W + (ml0 + 8) * HST + kp] = packhi16(v2, v3);
            }
        }
    }
    __syncthreads();

    // ---- phase B: cand = hidden @ W2 ----
    auto stageB = [&](int kt, int buf) {
        int kp = kt * 8 + sw;
        cpa16(smb + (SB_W + buf * 1536 + am * ST + sw) * 4,
              g_w2h + (size_t)am * 128 + kp);
    };

    stageB(0, 0);
    CP_COMMIT();
    CP_WAIT0();
    __syncthreads();

#pragma unroll
    for (int i = 0; i < 2; i++)
#pragma unroll
        for (int j = 0; j < 8; j++)
#pragma unroll
            for (int k = 0; k < 4; k++) acc[i][j][k] = 0.f;

    const int KT = NH / 16;
    for (int kt = 0; kt < KT; ++kt) {
        int cur = kt & 1;
        if (kt < KT - 1) {
            stageB(kt + 1, cur ^ 1);
            CP_COMMIT();
        }
        uint32_t aH[2][4];
#pragma unroll
        for (int mf = 0; mf < 2; mf++)
            ldsm4(aH[mf], rHs + kt * 32 + mf * (16 * HST * 4));
#pragma unroll
        for (int j = 0; j < 4; j++) {
            uint32_t bH[4];
            ldsm4(bH, rSB + cur * BUFB + j * (16 * ST * 4));
#pragma unroll
            for (int mf = 0; mf < 2; mf++) {
                mma16f(acc[mf][2 * j],     aH[mf], bH[0], bH[1]);
                mma16f(acc[mf][2 * j + 1], aH[mf], bH[2], bH[3]);
            }
        }
        if (kt < KT - 1) CP_WAIT0();
        __syncthreads();
    }

    // acc += b2 -> cand
#pragma unroll
    for (int mf = 0; mf < 2; mf++)
#pragma unroll
        for (int nf = 0; nf < 8; nf++) {
            int c0 = wn + nf * 8 + quad * 2;
            float bb0 = b2[c0], bb1 = b2[c0 + 1];
            acc[mf][nf][0] += bb0; acc[mf][nf][1] += bb1;
            acc[mf][nf][2] += bb0; acc[mf][nf][3] += bb1;
        }

    // ---- epilogue pass 1 (hef-free): cand dots for gate AND readout ----
    float su0 = 0.f, su1 = 0.f, su2 = 0.f, su3 = 0.f;
    float sr0 = 0.f, sr1 = 0.f, sr2 = 0.f, sr3 = 0.f;
#pragma unroll
    for (int mf = 0; mf < 2; mf++) {
#pragma unroll
        for (int nf = 0; nf < 8; nf++) {
            int c = wn + nf * 8 + quad * 2;
            float2 wc = *(const float2*)&Wupd[400 + c];
            float2 wr = *(const float2*)&Wread[256 + c];
            float a0 = acc[mf][nf][0], a1 = acc[mf][nf][1];
            float a2 = acc[mf][nf][2], a3 = acc[mf][nf][3];
            if (mf == 0) {
                su0 += a0 * wc.x + a1 * wc.y; sr0 += a0 * wr.x + a1 * wr.y;
                su1 += a2 * wc.x + a3 * wc.y; sr1 += a2 * wr.x + a3 * wr.y;
            } else {
                su2 += a0 * wc.x + a1 * wc.y; sr2 += a0 * wr.x + a1 * wr.y;
                su3 += a2 * wc.x + a3 * wc.y; sr3 += a2 * wr.x + a3 * wr.y;
            }
        }
    }
    su0 += __shfl_xor_sync(0xffffffffu, su0, 1); su0 += __shfl_xor_sync(0xffffffffu, su0, 2);
    su1 += __shfl_xor_sync(0xffffffffu, su1, 1); su1 += __shfl_xor_sync(0xffffffffu, su1, 2);
    su2 += __shfl_xor_sync(0xffffffffu, su2, 1); su2 += __shfl_xor_sync(0xffffffffu, su2, 2);
    su3 += __shfl_xor_sync(0xffffffffu, su3, 1); su3 += __shfl_xor_sync(0xffffffffu, su3, 2);
    sr0 += __shfl_xor_sync(0xffffffffu, sr0, 1); sr0 += __shfl_xor_sync(0xffffffffu, sr0, 2);
    sr1 += __shfl_xor_sync(0xffffffffu, sr1, 1); sr1 += __shfl_xor_sync(0xffffffffu, sr1, 2);
    sr2 += __shfl_xor_sync(0xffffffffu, sr2, 1); sr2 += __shfl_xor_sync(0xffffffffu, sr2, 2);
    sr3 += __shfl_xor_sync(0xffffffffu, sr3, 1); sr3 += __shfl_xor_sync(0xffffffffu, sr3, 2);
    if (quad == 0) {
        int nh = w >> 2;
        sred[(wm + grp) * 4 + nh * 2 + 0] = su0;
        sred[(wm + grp) * 4 + nh * 2 + 1] = sr0;
        sred[(wm + 8 + grp) * 4 + nh * 2 + 0] = su1;
        sred[(wm + 8 + grp) * 4 + nh * 2 + 1] = sr1;
        sred[(wm + 16 + grp) * 4 + nh * 2 + 0] = su2;
        sred[(wm + 16 + grp) * 4 + nh * 2 + 1] = sr2;
        sred[(wm + 24 + grp) * 4 + nh * 2 + 0] = su3;
        sred[(wm + 24 + grp) * 4 + nh * 2 + 1] = sr3;
    }
    __syncthreads();
    if (t < 128) {
        int e = me0 + t, r = srol[t], c = scol[t];
        float su = sred[t * 4 + 0] + sred[t * 4 + 2];
        float sr = sred[t * 4 + 1] + sred[t * 4 + 3];
        float gv = su + g_eproj[e * 4 + 0] + g_nproj[r * 8 + 2] + g_nproj[c * 8 + 3] + bupd[0];
        float g = 1.f / (1.f + expf(-gv));
        sg[t] = g;
        float rl = g * sr + (1.f - g) * g_eproj[e * 4 + 2] + g_eproj[e * 4 + 1]
                 + g_nproj[r * 8 + 4] + g_nproj[c * 8 + 5] + bread[0];
        g_rw[e] = expf(rl);
    }
    __syncthreads();

    // ---- epilogue pass 2: ef = g*cand + (1-g)*hef, write out (single hef read) ----
#pragma unroll
    for (int mf = 0; mf < 2; mf++) {
        int r0 = wm + mf * 16 + grp;
        float g0 = sg[r0], g1 = sg[r0 + 8];
#pragma unroll
        for (int nf = 0; nf < 8; nf++) {
            int c = wn + nf * 8 + quad * 2;
            float2 h0 = *(const float2*)&hef[(size_t)(me0 + r0) * 128 + c];
            float2 h1 = *(const float2*)&hef[(size_t)(me0 + r0 + 8) * 128 + c];
            float2 e0, e1;
            e0.x = fmaf(g0, acc[mf][nf][0] - h0.x, h0.x);
            e0.y = fmaf(g0, acc[mf][nf][1] - h0.y, h0.y);
            e1.x = fmaf(g1, acc[mf][nf][2] - h1.x, h1.x);
            e1.y = fmaf(g1, acc[mf][nf][3] - h1.y, h1.y);
            *(float2*)&out[(size_t)(me0 + r0) * 128 + c] = e0;
            *(float2*)&out[(size_t)(me0 + r0 + 8) * 128 + c] = e1;
        }
    }
}

// ---------------- readout: unnormalized scatter + segment sum ----------------
__global__ void k_rscatter(const int* __restrict__ ei, const int* __restrict__ batch,
                           const float* __restrict__ out) {
    __shared__ float sacc[NG * DE];
    __shared__ float ssum[NG];
    int t = threadIdx.x;
    for (int i = t; i < NG * DE; i += 256) sacc[i] = 0.f;
    if (t < NG) ssum[t] = 0.f;
    __syncthreads();
    int warp = t >> 5, lane = t & 31;
    for (int e = blockIdx.x * 8 + warp; e < NE; e += gridDim.x * 8) {
        int gi = batch[ei[e]];
        float rw = g_rw[e];
        float4 ef = ((const float4*)out)[e * 32 + lane];
        float* p = &sacc[gi * 128 + lane * 4];
        atomicAdd(p + 0, rw * ef.x);
        atomicAdd(p + 1, rw * ef.y);
        atomicAdd(p + 2, rw * ef.z);
        atomicAdd(p + 3, rw * ef.w);
        if (lane == 0) atomicAdd(&ssum[gi], rw);
    }
    __syncthreads();
    for (int i = t; i < NG * DE; i += 256)
        if (sacc[i] != 0.f) atomicAdd(&g_graphfeat[i], sacc[i]);
    if (t < NG && ssum[t] != 0.f) atomicAdd(&g_gsum[t], ssum[t]);
}

// ---------------- confidence ----------------
__global__ void k_conf(const float* __restrict__ Wscore, const float* __restrict__ bscore,
                       float* __restrict__ out) {
    int g = blockIdx.x, t = threadIdx.x;
    float v = g_graphfeat[g * 128 + t] / (g_gsum[g] + 1e-16f) * Wscore[t];
    v = wred(v);
    __shared__ float sm[4];
    if ((t & 31) == 0) sm[t >> 5] = v;
    __syncthreads();
    if (t == 0) {
        float s = sm[0] + sm[1] + sm[2] + sm[3] + bscore[0];
        out[(size_t)NE * DE + g] = 1.f / (1.f + expf(-s));
    }
}

// ---------------- launch ----------------
extern "C" void kernel_launch(void* const* d_in, const int* in_sizes, int n_in,
                              void* d_out, int out_size) {
    const float* x      = (const float*)d_in[0];
    const float* hef    = (const float*)d_in[1];
    const float* attr   = (const float*)d_in[2];
    const int*   ei     = (const int*)d_in[3];
    const int*   batch  = (const int*)d_in[4];
    const float* Wagg   = (const float*)d_in[6];
    const float* bagg   = (const float*)d_in[7];
    const float* W1     = (const float*)d_in[8];
    const float* b1     = (const float*)d_in[9];
    const float* W2     = (const float*)d_in[10];
    const float* b2     = (const float*)d_in[11];
    const float* Wupd   = (const float*)d_in[12];
    const float* bupd   = (const float*)d_in[13];
    const float* Wread  = (const float*)d_in[14];
    const float* bread  = (const float*)d_in[15];
    const float* Wscore = (const float*)d_in[16];
    const float* bscore = (const float*)d_in[17];
    float* out = (float*)d_out;

    static bool attr_set = false;
    if (!attr_set) {
        cudaFuncSetAttribute(k_nodegemm, cudaFuncAttributeMaxDynamicSharedMemorySize, NGM_WORDS * 4);
        cudaFuncSetAttribute(k_edge, cudaFuncAttributeMaxDynamicSharedMemorySize, EF_WORDS * 4);
        attr_set = true;
    }

    k_prep<<<(NE * 8 + 255) / 256, 256>>>(x, attr, W1, W2, Wagg, Wupd, Wread);
    k_aggscatter<<<NE / 8, 256>>>(hef, attr, ei, Wagg, bagg, Wupd, Wread);
    k_nnorm<<<(NN * 64 + 255) / 256, 256>>>();
    k_nodegemm<<<dim3((NN + 127) / 128, 4), 256, NGM_WORDS * 4>>>();
    k_edge<<<NE / 128, 256, EF_WORDS * 4>>>(hef, ei, b1, b2, Wupd, bupd,
                                            Wread, bread, out);
    k_rscatter<<<296, 256>>>(ei, batch, out);
    k_conf<<<NG, 128>>>(Wscore, bscore, out);
}